// round 3
// baseline (speedup 1.0000x reference)
#include <cuda_runtime.h>
#include <cstdint>

#define NN   8192
#define EE   65536
#define IND  128
#define HID  64
#define RDIM 4096   // HID*HID

// ---------------- static scratch (no allocs allowed) ----------------
__device__ float g_A[(size_t)NN * RDIM];   // A' [n][d*64 + j], BN-scale folded  (128 MB)
__device__ float g_S[NN * 192];            // per-node: p2(0..63) | qs(64..127) | qd(128..191)
__device__ float g_W1f[RDIM * IND];        // folded big weight, row r = d*64+j
__device__ float g_b1f[RDIM];
__device__ float g_WsmT[IND * 192];        // small weights, [k][c] transposed
__device__ float g_bsm[192];
__device__ float g_Call[HID];              // folded constant per output channel
__device__ int   g_hist[NN];
__device__ int   g_off[NN + 1];
__device__ int   g_cursor[NN];
__device__ int   g_sorted[EE];

// ---------------- weight folding ----------------
// W1f[r=d*64+j'][k] = s[j'] * sum_j ep3_w[j',j] * proj1_w[(j*64+d)][k]
__global__ void k_fold1(const float* __restrict__ p1w, const float* __restrict__ p1b,
                        const float* __restrict__ e3w,
                        const float* __restrict__ gam, const float* __restrict__ var) {
    int r = blockIdx.x;            // 0..4095
    int k = threadIdx.x;           // 0..127
    int jp = r & 63, d = r >> 6;
    float s = gam[jp] * rsqrtf(var[jp] + 1e-5f);
    float acc = 0.f;
#pragma unroll 8
    for (int j = 0; j < 64; ++j)
        acc += e3w[jp * 64 + j] * p1w[(size_t)((j << 6) | d) * IND + k];
    g_W1f[(size_t)r * IND + k] = s * acc;
    if (k == 0) {
        float b = 0.f;
        for (int j = 0; j < 64; ++j) b += e3w[jp * 64 + j] * p1b[(j << 6) | d];
        g_b1f[r] = s * b;
    }
}

// Small weights: rows 0..63 = proj2 (bias b2); 64..127 = s*M0 (src conv path);
// 128..191 = s*M1 (dst conv path). M_c[j][m] = sum_u conv_w[c][u]*ep2_w[j][m-u+1].
__global__ void k_fold2(const float* __restrict__ p2w, const float* __restrict__ p2b,
                        const float* __restrict__ convw, const float* __restrict__ e2w,
                        const float* __restrict__ gam, const float* __restrict__ var) {
    int c = blockIdx.x;            // 0..191
    int k = threadIdx.x;           // 0..127  (= m)
    float val;
    if (c < 64) {
        val = p2w[c * IND + k];
        if (k == 0) g_bsm[c] = p2b[c];
    } else {
        int j  = (c - 64) & 63;
        int cc = (c >= 128) ? 1 : 0;
        float s = gam[j] * rsqrtf(var[j] + 1e-5f);
        float a = 0.f;
#pragma unroll
        for (int u = 0; u < 3; ++u) {
            int i = k - u + 1;
            if (i >= 0 && i < IND) a += convw[cc * 3 + u] * e2w[j * IND + i];
        }
        val = s * a;
        if (k == 0) g_bsm[c] = 0.f;
    }
    g_WsmT[k * 192 + c] = val;
}

// Call[j] = s[j]*(conv_b*sum_i ep2_w[j,i] + ep2_b[j] + ep3_b[j]) + (beta - mean*s)
__global__ void k_call(const float* __restrict__ e2w, const float* __restrict__ e2b,
                       const float* __restrict__ e3b, const float* __restrict__ convb,
                       const float* __restrict__ gam, const float* __restrict__ bet,
                       const float* __restrict__ mean, const float* __restrict__ var) {
    int j = threadIdx.x;
    float s = gam[j] * rsqrtf(var[j] + 1e-5f);
    float t = bet[j] - mean[j] * s;
    float rs = 0.f;
    for (int i = 0; i < IND; ++i) rs += e2w[j * IND + i];
    g_Call[j] = s * (convb[0] * rs + e2b[j] + e3b[j]) + t;
}

// ---------------- small GEMM: S = h @ WsmT (+bias), [8192x128]@[128x192] ----------------
__global__ void k_sgemm_small(const float* __restrict__ h) {
    __shared__ __align__(16) float hs[IND * 32];   // [k][m]
    int t  = threadIdx.x;            // 0..191 -> output column c
    int n0 = blockIdx.x * 32;
    for (int idx = t; idx < 32 * IND; idx += 192) {
        int m = idx >> 7, k = idx & 127;
        hs[k * 32 + m] = h[(size_t)(n0 + m) * IND + k];
    }
    __syncthreads();
    float acc[32];
    float bias = g_bsm[t];
#pragma unroll
    for (int m = 0; m < 32; ++m) acc[m] = bias;
    for (int k = 0; k < IND; ++k) {
        float w = g_WsmT[k * 192 + t];
        const float4* h4 = (const float4*)&hs[k * 32];
#pragma unroll
        for (int m4 = 0; m4 < 8; ++m4) {
            float4 hv = h4[m4];
            acc[m4 * 4 + 0] += w * hv.x;
            acc[m4 * 4 + 1] += w * hv.y;
            acc[m4 * 4 + 2] += w * hv.z;
            acc[m4 * 4 + 3] += w * hv.w;
        }
    }
    for (int m = 0; m < 32; ++m) g_S[(size_t)(n0 + m) * 192 + t] = acc[m];
}

// ---------------- big GEMM: A' = h @ W1f^T + b1f, [8192x128]@[128x4096] ----------------
__global__ __launch_bounds__(256) void k_gemm_big(const float* __restrict__ h) {
    __shared__ __align__(16) float hs[32 * 132];
    __shared__ __align__(16) float ws[32 * 132];
    int tid = threadIdx.x;
    int tm = tid >> 4, tn = tid & 15;
    int m0 = blockIdx.y * 128, r0 = blockIdx.x * 128;
    float acc[8][8];
#pragma unroll
    for (int i = 0; i < 8; ++i)
#pragma unroll
        for (int j = 0; j < 8; ++j) acc[i][j] = 0.f;

    for (int ks = 0; ks < IND; ks += 32) {
#pragma unroll
        for (int i = 0; i < 4; ++i) {
            int f = tid + i * 256;        // 0..1023
            int m = f >> 3, kq = f & 7;   // m:0..127, kq:0..7 (4 floats each)
            float4 v = *(const float4*)&h[(size_t)(m0 + m) * IND + ks + kq * 4];
            hs[(kq * 4 + 0) * 132 + m] = v.x;
            hs[(kq * 4 + 1) * 132 + m] = v.y;
            hs[(kq * 4 + 2) * 132 + m] = v.z;
            hs[(kq * 4 + 3) * 132 + m] = v.w;
            float4 w = *(const float4*)&g_W1f[(size_t)(r0 + m) * IND + ks + kq * 4];
            ws[(kq * 4 + 0) * 132 + m] = w.x;
            ws[(kq * 4 + 1) * 132 + m] = w.y;
            ws[(kq * 4 + 2) * 132 + m] = w.z;
            ws[(kq * 4 + 3) * 132 + m] = w.w;
        }
        __syncthreads();
#pragma unroll 8
        for (int kk = 0; kk < 32; ++kk) {
            float a[8], b[8];
            *(float4*)(a)     = *(float4*)&hs[kk * 132 + tm * 8];
            *(float4*)(a + 4) = *(float4*)&hs[kk * 132 + tm * 8 + 4];
            *(float4*)(b)     = *(float4*)&ws[kk * 132 + tn * 8];
            *(float4*)(b + 4) = *(float4*)&ws[kk * 132 + tn * 8 + 4];
#pragma unroll
            for (int i = 0; i < 8; ++i)
#pragma unroll
                for (int j = 0; j < 8; ++j) acc[i][j] += a[i] * b[j];
        }
        __syncthreads();
    }

    float bias[8];
    *(float4*)(bias)     = *(const float4*)&g_b1f[r0 + tn * 8];
    *(float4*)(bias + 4) = *(const float4*)&g_b1f[r0 + tn * 8 + 4];
#pragma unroll
    for (int i = 0; i < 8; ++i) {
        float4 v0, v1;
        v0.x = acc[i][0] + bias[0]; v0.y = acc[i][1] + bias[1];
        v0.z = acc[i][2] + bias[2]; v0.w = acc[i][3] + bias[3];
        v1.x = acc[i][4] + bias[4]; v1.y = acc[i][5] + bias[5];
        v1.z = acc[i][6] + bias[6]; v1.w = acc[i][7] + bias[7];
        size_t base = (size_t)(m0 + tm * 8 + i) * RDIM + r0 + tn * 8;
        *(float4*)&g_A[base]     = v0;
        *(float4*)&g_A[base + 4] = v1;
    }
}

// ---------------- counting sort of edges by src ----------------
__global__ void k_zero_hist() {
    int i = blockIdx.x * blockDim.x + threadIdx.x;
    if (i < NN) g_hist[i] = 0;
}
__global__ void k_hist(const int* __restrict__ src) {
    int e = blockIdx.x * blockDim.x + threadIdx.x;
    if (e < EE) atomicAdd(&g_hist[src[e]], 1);
}
__global__ void k_scan() {
    __shared__ int sm[1024];
    int t = threadIdx.x;
    int base = t * 8;
    int p = 0;
#pragma unroll
    for (int i = 0; i < 8; ++i) p += g_hist[base + i];
    sm[t] = p;
    __syncthreads();
    int val = p;
    for (int off = 1; off < 1024; off <<= 1) {
        int v = 0;
        if (t >= off) v = sm[t - off];
        __syncthreads();
        if (t >= off) { val += v; sm[t] = val; }
        __syncthreads();
    }
    int run = val - p;   // exclusive prefix
#pragma unroll
    for (int i = 0; i < 8; ++i) {
        g_off[base + i]    = run;
        g_cursor[base + i] = run;
        run += g_hist[base + i];
    }
    if (t == 1023) g_off[NN] = run;
}
__global__ void k_scatter(const int* __restrict__ src) {
    int e = blockIdx.x * blockDim.x + threadIdx.x;
    if (e < EE) {
        int p = atomicAdd(&g_cursor[src[e]], 1);
        g_sorted[p] = e;
    }
}

// ---------------- edge kernel: out[e] = relu(A'[src]·p2[dst] + qs + qd + C) --------------
__global__ __launch_bounds__(64) void k_edge(const int* __restrict__ dst,
                                             float* __restrict__ out) {
    int n = blockIdx.x;
    int beg = g_off[n], end = g_off[n + 1];
    if (beg == end) return;
    int j = threadIdx.x;       // output channel 0..63
    int lane = j & 31;

    float Areg[64];            // A'[n][j][d] for d=0..63  (layout r = d*64+j)
    const float* Ap = &g_A[(size_t)n * RDIM + j];
#pragma unroll
    for (int d = 0; d < 64; ++d) Areg[d] = Ap[d * 64];

    float cj = g_Call[j] + g_S[(size_t)n * 192 + 64 + j];   // const + qs[src]

    for (int idx = beg; idx < end; ++idx) {
        int e = g_sorted[idx];
        int m = dst[e];
        const float* Sp = &g_S[(size_t)m * 192];
        float p2lo = Sp[lane];
        float p2hi = Sp[32 + lane];
        float acc = cj + Sp[128 + j];                        // + qd[dst]
#pragma unroll
        for (int d = 0; d < 32; ++d)
            acc += Areg[d] * __shfl_sync(0xffffffffu, p2lo, d);
#pragma unroll
        for (int d = 0; d < 32; ++d)
            acc += Areg[32 + d] * __shfl_sync(0xffffffffu, p2hi, d);
        out[(size_t)e * 64 + j] = fmaxf(acc, 0.f);
    }
}

// ---------------- launch ----------------
extern "C" void kernel_launch(void* const* d_in, const int* in_sizes, int n_in,
                              void* d_out, int out_size) {
    const float* h     = (const float*)d_in[0];
    const int*   src   = (const int*)  d_in[1];
    const int*   dst   = (const int*)  d_in[2];
    const float* p1w   = (const float*)d_in[3];
    const float* p1b   = (const float*)d_in[4];
    const float* p2w   = (const float*)d_in[5];
    const float* p2b   = (const float*)d_in[6];
    const float* convw = (const float*)d_in[7];
    const float* convb = (const float*)d_in[8];
    const float* e2w   = (const float*)d_in[9];
    const float* e2b   = (const float*)d_in[10];
    const float* e3w   = (const float*)d_in[11];
    const float* e3b   = (const float*)d_in[12];
    const float* gam   = (const float*)d_in[13];
    const float* bet   = (const float*)d_in[14];
    const float* mean  = (const float*)d_in[15];
    const float* var   = (const float*)d_in[16];
    float* out = (float*)d_out;

    k_fold1<<<RDIM, IND>>>(p1w, p1b, e3w, gam, var);
    k_fold2<<<192, IND>>>(p2w, p2b, convw, e2w, gam, var);
    k_call<<<1, 64>>>(e2w, e2b, e3b, convb, gam, bet, mean, var);
    k_sgemm_small<<<NN / 32, 192>>>(h);
    k_gemm_big<<<dim3(RDIM / 128, NN / 128), 256>>>(h);
    k_zero_hist<<<(NN + 255) / 256, 256>>>();
    k_hist<<<(EE + 255) / 256, 256>>>(src);
    k_scan<<<1, 1024>>>();
    k_scatter<<<(EE + 255) / 256, 256>>>(src);
    k_edge<<<NN, 64>>>(dst, out);
}

// round 5
// speedup vs baseline: 1.7957x; 1.7957x over previous
#include <cuda_runtime.h>
#include <cuda_bf16.h>
#include <cstdint>

#define NN   8192
#define EE   65536
#define IND  128
#define HID  64
#define RDIM 4096   // HID*HID

// ---------------- static scratch (no allocs allowed) ----------------
__device__ float g_A[(size_t)NN * RDIM];       // A' [n][d*64 + j], BN folded (128 MB)
__device__ float g_S[NN * 192];                // per-node: p2 | qs | qd
__device__ float g_W1f[RDIM * IND];            // folded big weight
__device__ float g_b1f[RDIM];
__device__ float g_WsmT[IND * 192];
__device__ float g_bsm[192];
__device__ float g_Call[HID];
__device__ __nv_bfloat16 g_Hhi[(size_t)NN * IND];
__device__ __nv_bfloat16 g_Hlo[(size_t)NN * IND];
__device__ __nv_bfloat16 g_Whi[(size_t)RDIM * IND];
__device__ __nv_bfloat16 g_Wlo[(size_t)RDIM * IND];
__device__ int   g_hist[NN];
__device__ int   g_off[NN + 1];
__device__ int   g_cursor[NN];
__device__ int   g_sorted[EE];

// ---------------- helpers ----------------
__device__ __forceinline__ uint32_t smem_u32(const void* p) {
    uint32_t a;
    asm("{ .reg .u64 t; cvta.to.shared.u64 t, %1; cvt.u32.u64 %0, t; }" : "=r"(a) : "l"(p));
    return a;
}
__device__ __forceinline__ void ldm4(uint32_t* r, uint32_t addr) {
    asm volatile("ldmatrix.sync.aligned.m8n8.x4.shared.b16 {%0,%1,%2,%3}, [%4];"
                 : "=r"(r[0]), "=r"(r[1]), "=r"(r[2]), "=r"(r[3]) : "r"(addr));
}
__device__ __forceinline__ void mma16816(float* d, const uint32_t* a, uint32_t b0, uint32_t b1) {
    asm volatile(
        "mma.sync.aligned.m16n8k16.row.col.f32.bf16.bf16.f32 "
        "{%0,%1,%2,%3}, {%4,%5,%6,%7}, {%8,%9}, {%0,%1,%2,%3};"
        : "+f"(d[0]), "+f"(d[1]), "+f"(d[2]), "+f"(d[3])
        : "r"(a[0]), "r"(a[1]), "r"(a[2]), "r"(a[3]), "r"(b0), "r"(b1));
}

// ---------------- weight folding ----------------
__global__ void k_fold1(const float* __restrict__ p1w, const float* __restrict__ p1b,
                        const float* __restrict__ e3w,
                        const float* __restrict__ gam, const float* __restrict__ var) {
    int r = blockIdx.x;            // 0..4095
    int k = threadIdx.x;           // 0..127
    int jp = r & 63, d = r >> 6;
    float s = gam[jp] * rsqrtf(var[jp] + 1e-5f);
    float acc = 0.f;
#pragma unroll 8
    for (int j = 0; j < 64; ++j)
        acc += e3w[jp * 64 + j] * p1w[(size_t)((j << 6) | d) * IND + k];
    g_W1f[(size_t)r * IND + k] = s * acc;
    if (k == 0) {
        float b = 0.f;
        for (int j = 0; j < 64; ++j) b += e3w[jp * 64 + j] * p1b[(j << 6) | d];
        g_b1f[r] = s * b;
    }
}

__global__ void k_fold2(const float* __restrict__ p2w, const float* __restrict__ p2b,
                        const float* __restrict__ convw, const float* __restrict__ e2w,
                        const float* __restrict__ gam, const float* __restrict__ var) {
    int c = blockIdx.x;            // 0..191
    int k = threadIdx.x;           // 0..127
    float val;
    if (c < 64) {
        val = p2w[c * IND + k];
        if (k == 0) g_bsm[c] = p2b[c];
    } else {
        int j  = (c - 64) & 63;
        int cc = (c >= 128) ? 1 : 0;
        float s = gam[j] * rsqrtf(var[j] + 1e-5f);
        float a = 0.f;
#pragma unroll
        for (int u = 0; u < 3; ++u) {
            int i = k - u + 1;
            if (i >= 0 && i < IND) a += convw[cc * 3 + u] * e2w[j * IND + i];
        }
        val = s * a;
        if (k == 0) g_bsm[c] = 0.f;
    }
    g_WsmT[k * 192 + c] = val;
}

__global__ void k_call(const float* __restrict__ e2w, const float* __restrict__ e2b,
                       const float* __restrict__ e3b, const float* __restrict__ convb,
                       const float* __restrict__ gam, const float* __restrict__ bet,
                       const float* __restrict__ mean, const float* __restrict__ var) {
    int j = threadIdx.x;
    float s = gam[j] * rsqrtf(var[j] + 1e-5f);
    float t = bet[j] - mean[j] * s;
    float rs = 0.f;
    for (int i = 0; i < IND; ++i) rs += e2w[j * IND + i];
    g_Call[j] = s * (convb[0] * rs + e2b[j] + e3b[j]) + t;
}

// ---------------- bf16 split conversion ----------------
__global__ void k_convert_h(const float* __restrict__ h) {
    int i = blockIdx.x * 256 + threadIdx.x;
    float x = h[i];
    __nv_bfloat16 hi = __float2bfloat16(x);
    g_Hhi[i] = hi;
    g_Hlo[i] = __float2bfloat16(x - __bfloat162float(hi));
}
__global__ void k_convert_w() {
    int i = blockIdx.x * 256 + threadIdx.x;
    float x = g_W1f[i];
    __nv_bfloat16 hi = __float2bfloat16(x);
    g_Whi[i] = hi;
    g_Wlo[i] = __float2bfloat16(x - __bfloat162float(hi));
}

// ---------------- small GEMM: S = h @ WsmT (+bias) ----------------
__global__ __launch_bounds__(192) void k_sgemm_small(const float* __restrict__ h) {
    __shared__ __align__(16) float hs[IND * 16];   // [k][m]
    int t  = threadIdx.x;            // 0..191 -> output column c
    int n0 = blockIdx.x * 16;
    for (int idx = t; idx < 16 * IND; idx += 192) {
        int m = idx >> 7, k = idx & 127;
        hs[k * 16 + m] = h[(size_t)(n0 + m) * IND + k];
    }
    __syncthreads();
    float acc[16];
    float bias = g_bsm[t];
#pragma unroll
    for (int m = 0; m < 16; ++m) acc[m] = bias;
    for (int k = 0; k < IND; ++k) {
        float w = g_WsmT[k * 192 + t];
        const float4* h4 = (const float4*)&hs[k * 16];
#pragma unroll
        for (int m4 = 0; m4 < 4; ++m4) {
            float4 hv = h4[m4];
            acc[m4 * 4 + 0] += w * hv.x;
            acc[m4 * 4 + 1] += w * hv.y;
            acc[m4 * 4 + 2] += w * hv.z;
            acc[m4 * 4 + 3] += w * hv.w;
        }
    }
#pragma unroll
    for (int m = 0; m < 16; ++m) g_S[(size_t)(n0 + m) * 192 + t] = acc[m];
}

// ---------------- big GEMM via legacy mma.sync (bf16 split x3) ----------------
// CTA tile 128x128, K=128 in smem. 8 warps in 2x4 (wm x wn); warp tile 64x32.
// SMEM tile layout: row*256B, 16-byte chunk c swizzled c ^= (row & 7) (low 3 bits).
#define SA_HI 0
#define SA_LO 32768
#define SB_HI 65536
#define SB_LO 98304
#define GEMM_SMEM 131072

__device__ __forceinline__ void ld_tile(const __nv_bfloat16* __restrict__ src,
                                        int row0, char* dst, int tid) {
    int row = tid >> 1;               // 0..127
    int c0  = (tid & 1) * 8;          // first chunk
    const uint4* s = (const uint4*)(src + (size_t)(row0 + row) * IND) + c0;
    char* drow = dst + row * 256;
    int sw = row & 7;
#pragma unroll
    for (int c = 0; c < 8; ++c) {
        int ch = c0 + c;
        *(uint4*)(drow + (((ch & 7) ^ sw) << 4) + ((ch & 8) << 4)) = s[c];
    }
}

__global__ __launch_bounds__(256) void k_gemm_mma() {
    extern __shared__ char smem[];
    int tid = threadIdx.x;
    int warp = tid >> 5, lane = tid & 31;
    int r0 = blockIdx.x * 128;     // N (W1f rows)
    int m0 = blockIdx.y * 128;     // M (nodes)

    ld_tile(g_Hhi, m0, smem + SA_HI, tid);
    ld_tile(g_Hlo, m0, smem + SA_LO, tid);
    ld_tile(g_Whi, r0, smem + SB_HI, tid);
    ld_tile(g_Wlo, r0, smem + SB_LO, tid);
    __syncthreads();

    int wm = warp & 1, wn = warp >> 1;          // 2 x 4
    uint32_t sbase = smem_u32(smem);

    float acc[4][4][4];
#pragma unroll
    for (int mt = 0; mt < 4; ++mt)
#pragma unroll
        for (int nt = 0; nt < 4; ++nt)
#pragma unroll
            for (int i = 0; i < 4; ++i) acc[mt][nt][i] = 0.f;

    int rbase = lane & 15;
    int khalf = (lane >> 4) << 3;               // 0 or 8

#pragma unroll 1
    for (int pass = 0; pass < 3; ++pass) {
        uint32_t aBase = sbase + ((pass == 2) ? SA_LO : SA_HI);
        uint32_t bBase = sbase + ((pass == 1) ? SB_LO : SB_HI);
#pragma unroll
        for (int ks = 0; ks < 8; ++ks) {
            int kk = ks * 16 + khalf;
            int kch = kk >> 3;                  // 0..15
            uint32_t a[4][4];
#pragma unroll
            for (int mt = 0; mt < 4; ++mt) {
                int row = wm * 64 + mt * 16 + rbase;
                uint32_t addr = aBase + row * 256 +
                                ((((kch & 7) ^ (row & 7)) << 4) + ((kch & 8) << 4));
                ldm4(a[mt], addr);
            }
            uint32_t b[2][4];
#pragma unroll
            for (int bt = 0; bt < 2; ++bt) {
                int row = wn * 32 + bt * 16 + rbase;
                uint32_t addr = bBase + row * 256 +
                                ((((kch & 7) ^ (row & 7)) << 4) + ((kch & 8) << 4));
                ldm4(b[bt], addr);
            }
#pragma unroll
            for (int mt = 0; mt < 4; ++mt)
#pragma unroll
                for (int nt = 0; nt < 4; ++nt)
                    mma16816(acc[mt][nt], a[mt],
                             b[nt >> 1][nt & 1], b[nt >> 1][(nt & 1) + 2]);
        }
    }

    // epilogue: add bias, store fp32 to g_A
    int gr = lane >> 2, gc = (lane & 3) * 2;
    float bias[4][2];
#pragma unroll
    for (int nt = 0; nt < 4; ++nt) {
        int col = r0 + wn * 32 + nt * 8 + gc;
        bias[nt][0] = g_b1f[col];
        bias[nt][1] = g_b1f[col + 1];
    }
#pragma unroll
    for (int mt = 0; mt < 4; ++mt) {
        int row = m0 + wm * 64 + mt * 16 + gr;
#pragma unroll
        for (int nt = 0; nt < 4; ++nt) {
            int col = r0 + wn * 32 + nt * 8 + gc;
            float2 v0, v1;
            v0.x = acc[mt][nt][0] + bias[nt][0];
            v0.y = acc[mt][nt][1] + bias[nt][1];
            v1.x = acc[mt][nt][2] + bias[nt][0];
            v1.y = acc[mt][nt][3] + bias[nt][1];
            *(float2*)&g_A[(size_t)row * RDIM + col]       = v0;
            *(float2*)&g_A[(size_t)(row + 8) * RDIM + col] = v1;
        }
    }
}

// ---------------- counting sort of edges by src ----------------
__global__ void k_zero_hist() {
    int i = blockIdx.x * blockDim.x + threadIdx.x;
    if (i < NN) g_hist[i] = 0;
}
__global__ void k_hist(const int* __restrict__ src) {
    int e = blockIdx.x * blockDim.x + threadIdx.x;
    if (e < EE) atomicAdd(&g_hist[src[e]], 1);
}
__global__ void k_scan() {
    __shared__ int sm[1024];
    int t = threadIdx.x;
    int base = t * 8;
    int p = 0;
#pragma unroll
    for (int i = 0; i < 8; ++i) p += g_hist[base + i];
    sm[t] = p;
    __syncthreads();
    int val = p;
    for (int off = 1; off < 1024; off <<= 1) {
        int v = 0;
        if (t >= off) v = sm[t - off];
        __syncthreads();
        if (t >= off) { val += v; sm[t] = val; }
        __syncthreads();
    }
    int run = val - p;
#pragma unroll
    for (int i = 0; i < 8; ++i) {
        g_off[base + i]    = run;
        g_cursor[base + i] = run;
        run += g_hist[base + i];
    }
    if (t == 1023) g_off[NN] = run;
}
__global__ void k_scatter(const int* __restrict__ src) {
    int e = blockIdx.x * blockDim.x + threadIdx.x;
    if (e < EE) {
        int p = atomicAdd(&g_cursor[src[e]], 1);
        g_sorted[p] = e;
    }
}

// ---------------- edge kernel ----------------
__global__ __launch_bounds__(64) void k_edge(const int* __restrict__ dst,
                                             float* __restrict__ out) {
    int n = blockIdx.x;
    int beg = g_off[n], end = g_off[n + 1];
    if (beg == end) return;
    int j = threadIdx.x;
    int lane = j & 31;

    float Areg[64];
    const float* Ap = &g_A[(size_t)n * RDIM + j];
#pragma unroll
    for (int d = 0; d < 64; ++d) Areg[d] = Ap[d * 64];

    float cj = g_Call[j] + g_S[(size_t)n * 192 + 64 + j];

    for (int idx = beg; idx < end; ++idx) {
        int e = g_sorted[idx];
        int m = dst[e];
        const float* Sp = &g_S[(size_t)m * 192];
        float p2lo = Sp[lane];
        float p2hi = Sp[32 + lane];
        float acc = cj + Sp[128 + j];
#pragma unroll
        for (int d = 0; d < 32; ++d)
            acc += Areg[d] * __shfl_sync(0xffffffffu, p2lo, d);
#pragma unroll
        for (int d = 0; d < 32; ++d)
            acc += Areg[32 + d] * __shfl_sync(0xffffffffu, p2hi, d);
        out[(size_t)e * 64 + j] = fmaxf(acc, 0.f);
    }
}

// ---------------- launch ----------------
extern "C" void kernel_launch(void* const* d_in, const int* in_sizes, int n_in,
                              void* d_out, int out_size) {
    const float* h     = (const float*)d_in[0];
    const int*   src   = (const int*)  d_in[1];
    const int*   dst   = (const int*)  d_in[2];
    const float* p1w   = (const float*)d_in[3];
    const float* p1b   = (const float*)d_in[4];
    const float* p2w   = (const float*)d_in[5];
    const float* p2b   = (const float*)d_in[6];
    const float* convw = (const float*)d_in[7];
    const float* convb = (const float*)d_in[8];
    const float* e2w   = (const float*)d_in[9];
    const float* e2b   = (const float*)d_in[10];
    const float* e3w   = (const float*)d_in[11];
    const float* e3b   = (const float*)d_in[12];
    const float* gam   = (const float*)d_in[13];
    const float* bet   = (const float*)d_in[14];
    const float* mean  = (const float*)d_in[15];
    const float* var   = (const float*)d_in[16];
    float* out = (float*)d_out;

    cudaFuncSetAttribute(k_gemm_mma, cudaFuncAttributeMaxDynamicSharedMemorySize, GEMM_SMEM);

    k_fold1<<<RDIM, IND>>>(p1w, p1b, e3w, gam, var);
    k_fold2<<<192, IND>>>(p2w, p2b, convw, e2w, gam, var);
    k_call<<<1, 64>>>(e2w, e2b, e3b, convb, gam, bet, mean, var);
    k_convert_h<<<NN * IND / 256, 256>>>(h);
    k_convert_w<<<RDIM * IND / 256, 256>>>();
    k_sgemm_small<<<NN / 16, 192>>>(h);
    k_gemm_mma<<<dim3(RDIM / 128, NN / 128), 256, GEMM_SMEM>>>();
    k_zero_hist<<<(NN + 255) / 256, 256>>>();
    k_hist<<<(EE + 255) / 256, 256>>>(src);
    k_scan<<<1, 1024>>>();
    k_scatter<<<(EE + 255) / 256, 256>>>(src);
    k_edge<<<NN, 64>>>(dst, out);
}